// round 13
// baseline (speedup 1.0000x reference)
#include <cuda_runtime.h>
#include <mma.h>
#include <cstdint>

using namespace nvcuda;

#define B_ 8
#define N_ 2000
#define F_ 128
#define K_ 64
#define TK_ 32
#define NT_ ((N_ + TK_ - 1) / TK_)   // 63

// -------- device scratch --------
__device__ float g_P [B_*N_*K_];
__device__ float g_AS[B_*N_*K_];
__device__ float g_Q [B_*N_];
__device__ float g_D [B_*N_];
__device__ float g_OUTADJ[B_*K_*K_];
__device__ float g_SS[B_*K_*K_];
__device__ float g_DEN[B_];
__device__ float g_LOSS[2*B_];

// -------- init --------
__global__ void k_init(float* __restrict__ out_region) {
    int i = blockIdx.x * blockDim.x + threadIdx.x;
    if (i < B_*K_*F_) out_region[i] = 0.f;
    if (i < B_*K_*K_) { g_OUTADJ[i] = 0.f; g_SS[i] = 0.f; }
    if (i < B_) g_DEN[i] = 0.f;
}

// -------- softmax over K=64, one warp per row --------
__global__ void k_softmax(const float* __restrict__ s,
                          const int* __restrict__ mask) {
    int row = (blockIdx.x * blockDim.x + threadIdx.x) >> 5;
    if (row >= B_*N_) return;
    int lane = threadIdx.x & 31;
    const float* sr = s + (size_t)row * K_;
    float v0 = sr[lane], v1 = sr[lane + 32];
    float mx = fmaxf(v0, v1);
    #pragma unroll
    for (int o = 16; o; o >>= 1) mx = fmaxf(mx, __shfl_xor_sync(0xffffffffu, mx, o));
    float e0 = expf(v0 - mx), e1 = expf(v1 - mx);
    float sm = e0 + e1;
    #pragma unroll
    for (int o = 16; o; o >>= 1) sm += __shfl_xor_sync(0xffffffffu, sm, o);
    float m = (mask[row] != 0) ? 1.f : 0.f;
    float inv = m / sm;
    float p0 = e0 * inv, p1 = e1 * inv;
    g_P[(size_t)row * K_ + lane]      = p0;
    g_P[(size_t)row * K_ + lane + 32] = p1;
    float q = p0 * p0 + p1 * p1;
    #pragma unroll
    for (int o = 16; o; o >>= 1) q += __shfl_xor_sync(0xffffffffu, q, o);
    if (lane == 0) g_Q[row] = q;
}

// -------- out[b,k,f] = P^T x (scalar fp32), 64-row tiles --------
__global__ void __launch_bounds__(256) k_out_gemm(const float* __restrict__ x,
                                                  float* __restrict__ out) {
    int b = blockIdx.y;
    int row0 = blockIdx.x * 64;
    int rows = min(64, N_ - row0);
    __shared__ float Ps[32][64];
    __shared__ float Xs[32][128];
    int tid = threadIdx.x;
    int kq = tid & 15;
    int fq = tid >> 4;
    float acc[4][8] = {};
    const float* Pb = g_P + (size_t)b * N_ * K_ + (size_t)row0 * K_;
    const float* Xb = x   + (size_t)b * N_ * F_ + (size_t)row0 * F_;
    for (int t0 = 0; t0 < rows; t0 += 32) {
        #pragma unroll
        for (int i = 0; i < 8; i++) {
            int idx = tid + i * 256;
            int r = idx >> 6, c = idx & 63;
            Ps[r][c] = (t0 + r < rows) ? Pb[(size_t)(t0 + r) * K_ + c] : 0.f;
        }
        #pragma unroll
        for (int i = 0; i < 16; i++) {
            int idx = tid + i * 256;
            int r = idx >> 7, c = idx & 127;
            Xs[r][c] = (t0 + r < rows) ? Xb[(size_t)(t0 + r) * F_ + c] : 0.f;
        }
        __syncthreads();
        #pragma unroll 8
        for (int m = 0; m < 32; m++) {
            float4 pv  = *(const float4*)&Ps[m][kq * 4];
            float4 xv0 = *(const float4*)&Xs[m][fq * 8];
            float4 xv1 = *(const float4*)&Xs[m][fq * 8 + 4];
            float a[4]  = {pv.x, pv.y, pv.z, pv.w};
            float bb[8] = {xv0.x, xv0.y, xv0.z, xv0.w, xv1.x, xv1.y, xv1.z, xv1.w};
            #pragma unroll
            for (int i = 0; i < 4; i++)
                #pragma unroll
                for (int j = 0; j < 8; j++)
                    acc[i][j] = fmaf(a[i], bb[j], acc[i][j]);
        }
        __syncthreads();
    }
    float* ob = out + (size_t)b * K_ * F_;
    #pragma unroll
    for (int i = 0; i < 4; i++)
        #pragma unroll
        for (int j = 0; j < 8; j++)
            atomicAdd(&ob[(kq * 4 + i) * F_ + fq * 8 + j], acc[i][j]);
}

// -------- AS = adj @ P via wmma tf32, 4-stage cp.async pipeline --------
#define APAD 36
#define BPAD 68
#define STAGES 4
#define A_FLOATS (64 * APAD)            // 2304 floats = 9216 B
#define B_FLOATS (TK_ * BPAD)           // 2176 floats = 8704 B
#define STAGE_FLOATS (A_FLOATS + B_FLOATS)
#define SMEM_ADJ_BYTES (STAGES * STAGE_FLOATS * 4)   // 71680

__device__ __forceinline__ uint32_t smem_addr(const void* p) {
    return (uint32_t)__cvta_generic_to_shared(p);
}

__global__ void __launch_bounds__(256) k_adj_wmma(const float* __restrict__ adj) {
    extern __shared__ float smem[];
    int tid = threadIdx.x;
    int warp = tid >> 5;
    int wm = warp >> 1;               // 0..3 (16-row tiles)
    int wn = warp & 1;                // 0..1 (32-col tiles)
    int b = blockIdx.y;
    int row0 = blockIdx.x * 64;
    int rows = min(64, N_ - row0);    // 64 or 16

    const float* Ab = adj + (size_t)b * N_ * N_;
    const float* Pb = g_P + (size_t)b * N_ * K_;

    wmma::fragment<wmma::accumulator, 16, 16, 8, float> c[2];
    wmma::fill_fragment(c[0], 0.f);
    wmma::fill_fragment(c[1], 0.f);
    float dsum = 0.f;

    auto issue = [&](int t) {
        int s = t % STAGES;
        float* As = smem + s * STAGE_FLOATS;
        float* Bs = As + A_FLOATS;
        int m0 = t * TK_;
        // A tile 64x32: 512 float4s, 2 per thread
        #pragma unroll
        for (int i = 0; i < 2; i++) {
            int idx = tid + i * 256;
            int r = idx >> 3, c4 = (idx & 7) * 4;
            bool ok = (r < rows) && (m0 + c4 < N_);
            const float* src = &Ab[(size_t)(row0 + (ok ? r : 0)) * N_ + (ok ? m0 + c4 : 0)];
            uint32_t dst = smem_addr(&As[r * APAD + c4]);
            int sz = ok ? 16 : 0;
            asm volatile("cp.async.cg.shared.global [%0], [%1], 16, %2;"
                         :: "r"(dst), "l"(src), "r"(sz));
        }
        // B tile 32x64: 512 float4s, 2 per thread
        #pragma unroll
        for (int i = 0; i < 2; i++) {
            int idx = tid + i * 256;
            int r = idx >> 4, c4 = (idx & 15) * 4;
            bool ok = (m0 + r < N_);
            const float* src = &Pb[(size_t)(ok ? m0 + r : 0) * K_ + c4];
            uint32_t dst = smem_addr(&Bs[r * BPAD + c4]);
            int sz = ok ? 16 : 0;
            asm volatile("cp.async.cg.shared.global [%0], [%1], 16, %2;"
                         :: "r"(dst), "l"(src), "r"(sz));
        }
        asm volatile("cp.async.commit_group;");
    };

    #pragma unroll
    for (int t = 0; t < STAGES - 1; t++) issue(t);

    int drow = tid >> 2;              // degree: 4 threads per row
    int dcol = (tid & 3) * 8;

    for (int t = 0; t < NT_; t++) {
        int s = t % STAGES;
        float* As = smem + s * STAGE_FLOATS;
        float* Bs = As + A_FLOATS;
        asm volatile("cp.async.wait_group %0;" :: "n"(STAGES - 2));
        __syncthreads();

        // degree partial from staged tile (raw fp32, zfilled tails are 0)
        {
            float4 v0 = *(const float4*)&As[drow * APAD + dcol];
            float4 v1 = *(const float4*)&As[drow * APAD + dcol + 4];
            dsum += v0.x + v0.y + v0.z + v0.w + v1.x + v1.y + v1.z + v1.w;
        }

        #pragma unroll
        for (int ks = 0; ks < 4; ks++) {
            wmma::fragment<wmma::matrix_a, 16, 16, 8, wmma::precision::tf32, wmma::row_major> af;
            wmma::fragment<wmma::matrix_b, 16, 16, 8, wmma::precision::tf32, wmma::row_major> bf[2];
            wmma::load_matrix_sync(af, &As[(wm * 16) * APAD + ks * 8], APAD);
            #pragma unroll
            for (int e = 0; e < af.num_elements; e++)
                af.x[e] = wmma::__float_to_tf32(af.x[e]);
            #pragma unroll
            for (int j = 0; j < 2; j++) {
                wmma::load_matrix_sync(bf[j], &Bs[(ks * 8) * BPAD + wn * 32 + j * 16], BPAD);
                #pragma unroll
                for (int e = 0; e < bf[j].num_elements; e++)
                    bf[j].x[e] = wmma::__float_to_tf32(bf[j].x[e]);
            }
            #pragma unroll
            for (int j = 0; j < 2; j++)
                wmma::mma_sync(c[j], af, bf[j], c[j]);
        }
        __syncthreads();
        if (t + STAGES - 1 < NT_) issue(t + STAGES - 1);
    }

    // degree: combine 4 threads per row, store
    dsum += __shfl_xor_sync(0xffffffffu, dsum, 1);
    dsum += __shfl_xor_sync(0xffffffffu, dsum, 2);
    if ((tid & 3) == 0 && drow < rows) g_D[b * N_ + row0 + drow] = dsum;

    // store fragments
    float* ASb = g_AS + ((size_t)b * N_ + row0) * K_;
    int r = wm * 16;
    if (r < rows) {
        #pragma unroll
        for (int j = 0; j < 2; j++)
            wmma::store_matrix_sync(&ASb[(size_t)r * K_ + wn * 32 + j * 16],
                                    c[j], K_, wmma::mem_row_major);
    }
}

// -------- out_adj = AS^T P, ss = P^T P, den = sum d*q (125-row chunks) --------
__global__ void __launch_bounds__(256) k_small(void) {
    int b = blockIdx.y;
    int n0 = blockIdx.x * 125;
    __shared__ float ASs[16][64];
    __shared__ float Ps[16][64];
    __shared__ float red[256];
    int tid = threadIdx.x;
    int kg = tid & 15;
    int lg = tid >> 4;
    float accA[4][4] = {};
    float accS[4][4] = {};
    const float* ASb = g_AS + (size_t)b * N_ * K_;
    const float* Pb  = g_P  + (size_t)b * N_ * K_;
    for (int t0 = 0; t0 < 125; t0 += 16) {
        #pragma unroll
        for (int i = 0; i < 4; i++) {
            int idx = tid + i * 256;
            int r = idx >> 6, c = idx & 63;
            bool ok = (t0 + r) < 125;
            size_t g = (size_t)(n0 + t0 + r) * K_ + c;
            ASs[r][c] = ok ? ASb[g] : 0.f;
            Ps[r][c]  = ok ? Pb[g]  : 0.f;
        }
        __syncthreads();
        #pragma unroll 8
        for (int m = 0; m < 16; m++) {
            float4 ak = *(const float4*)&ASs[m][kg * 4];
            float4 pk = *(const float4*)&Ps[m][kg * 4];
            float4 pl = *(const float4*)&Ps[m][lg * 4];
            float a[4] = {ak.x, ak.y, ak.z, ak.w};
            float p[4] = {pk.x, pk.y, pk.z, pk.w};
            float q[4] = {pl.x, pl.y, pl.z, pl.w};
            #pragma unroll
            for (int i = 0; i < 4; i++)
                #pragma unroll
                for (int j = 0; j < 4; j++) {
                    accA[i][j] = fmaf(a[i], q[j], accA[i][j]);
                    accS[i][j] = fmaf(p[i], q[j], accS[i][j]);
                }
        }
        __syncthreads();
    }
    float* OA  = g_OUTADJ + b * K_ * K_;
    float* SSb = g_SS     + b * K_ * K_;
    #pragma unroll
    for (int i = 0; i < 4; i++)
        #pragma unroll
        for (int j = 0; j < 4; j++) {
            atomicAdd(&OA [(kg * 4 + i) * K_ + lg * 4 + j], accA[i][j]);
            atomicAdd(&SSb[(kg * 4 + i) * K_ + lg * 4 + j], accS[i][j]);
        }
    float dq = 0.f;
    for (int n = tid; n < 125; n += 256) {
        int gi = b * N_ + n0 + n;
        dq += g_D[gi] * g_Q[gi];
    }
    red[tid] = dq; __syncthreads();
    for (int st = 128; st; st >>= 1) { if (tid < st) red[tid] += red[tid + st]; __syncthreads(); }
    if (tid == 0) atomicAdd(&g_DEN[b], red[0]);
}

// -------- per-batch finalize --------
__global__ void k_finalize(float* __restrict__ outadj_out) {
    int b = blockIdx.x;
    int tid = threadIdx.x;
    const float* OA  = g_OUTADJ + b * K_ * K_;
    const float* SSb = g_SS     + b * K_ * K_;
    __shared__ float red[256];
    __shared__ float s_frob, s_trace;
    __shared__ float dvec[K_];

    float fs = 0.f;
    for (int i = tid; i < K_*K_; i += 256) { float v = SSb[i]; fs += v * v; }
    red[tid] = fs; __syncthreads();
    for (int st = 128; st; st >>= 1) { if (tid < st) red[tid] += red[tid + st]; __syncthreads(); }
    if (tid == 0) s_frob = sqrtf(red[0]);
    __syncthreads();
    float frob = s_frob;

    float os = 0.f;
    for (int i = tid; i < K_*K_; i += 256) {
        int k = i >> 6, l = i & 63;
        float v = SSb[i] / frob - ((k == l) ? 0.125f : 0.f);
        os += v * v;
    }
    red[tid] = os; __syncthreads();
    for (int st = 128; st; st >>= 1) { if (tid < st) red[tid] += red[tid + st]; __syncthreads(); }
    float ortho = sqrtf(red[0]);
    __syncthreads();

    float tr = (tid < K_) ? OA[tid * K_ + tid] : 0.f;
    red[tid] = tr; __syncthreads();
    for (int st = 128; st; st >>= 1) { if (tid < st) red[tid] += red[tid + st]; __syncthreads(); }
    if (tid == 0) s_trace = red[0];
    __syncthreads();

    if (tid < K_) {
        float rs = 0.f;
        #pragma unroll
        for (int l = 0; l < K_; l++) if (l != tid) rs += OA[tid * K_ + l];
        dvec[tid] = sqrtf(rs) + 1e-15f;
    }
    __syncthreads();
    for (int i = tid; i < K_*K_; i += 256) {
        int k = i >> 6, l = i & 63;
        float v = (k == l) ? 0.f : OA[i] / (dvec[k] * dvec[l]);
        outadj_out[b * K_ * K_ + i] = v;
    }
    if (tid == 0) {
        g_LOSS[b]      = -(s_trace / g_DEN[b]);
        g_LOSS[B_ + b] = ortho;
    }
}

__global__ void k_losses(float* __restrict__ out2) {
    if (threadIdx.x == 0) {
        float a = 0.f, o = 0.f;
        #pragma unroll
        for (int b = 0; b < B_; b++) { a += g_LOSS[b]; o += g_LOSS[B_ + b]; }
        out2[0] = a * (1.f / B_);
        out2[1] = o * (1.f / B_);
    }
}

extern "C" void kernel_launch(void* const* d_in, const int* in_sizes, int n_in,
                              void* d_out, int out_size) {
    const float* x    = (const float*)d_in[0];   // [8,2000,128]
    const float* adj  = (const float*)d_in[1];   // [8,2000,2000]
    const float* s    = (const float*)d_in[2];   // [8,2000,64]
    const int*   mask = (const int*)d_in[3];     // [8,2000] bool->int32
    float* out = (float*)d_out;
    // layout: out [8,64,128] | out_adj [8,64,64] | mincut_loss | ortho_loss

    cudaFuncSetAttribute(k_adj_wmma, cudaFuncAttributeMaxDynamicSharedMemorySize,
                         SMEM_ADJ_BYTES);

    k_init<<<256, 256>>>(out);
    k_softmax<<<(B_*N_*32 + 255) / 256, 256>>>(s, mask);
    dim3 g2(32, B_);  k_out_gemm<<<g2, 256>>>(x, out);
    dim3 g3(32, B_);  k_adj_wmma<<<g3, 256, SMEM_ADJ_BYTES>>>(adj);
    dim3 g4(16, B_);  k_small<<<g4, 256>>>();
    k_finalize<<<B_, 256>>>(out + B_*K_*F_);
    k_losses<<<1, 32>>>(out + B_*K_*F_ + B_*K_*K_);
    (void)in_sizes; (void)n_in; (void)out_size;
}

// round 15
// speedup vs baseline: 1.0243x; 1.0243x over previous
#include <cuda_runtime.h>
#include <mma.h>
#include <cstdint>

using namespace nvcuda;

#define B_ 8
#define N_ 2000
#define F_ 128
#define K_ 64
#define TK_ 32
#define NT_ ((N_ + TK_ - 1) / TK_)   // 63 tiles
#define MSPLIT 2
#define TILES0 32                    // chunk0: tiles 0..31, chunk1: 32..62

// -------- device scratch --------
__device__ float g_P  [B_*N_*K_];
__device__ float g_AS [B_*N_*K_];    // partial AS, chunk 0
__device__ float g_AS2[B_*N_*K_];    // partial AS, chunk 1
__device__ float g_Q  [B_*N_];
__device__ float g_D  [B_*N_];       // partial degree, chunk 0
__device__ float g_D2 [B_*N_];       // partial degree, chunk 1
__device__ float g_OUTADJ[B_*K_*K_];
__device__ float g_SS[B_*K_*K_];
__device__ float g_DEN[B_];
__device__ float g_LOSS[2*B_];

// -------- init --------
__global__ void k_init(float* __restrict__ out_region) {
    int i = blockIdx.x * blockDim.x + threadIdx.x;
    if (i < B_*K_*F_) out_region[i] = 0.f;
    if (i < B_*K_*K_) { g_OUTADJ[i] = 0.f; g_SS[i] = 0.f; }
    if (i < B_) g_DEN[i] = 0.f;
}

// -------- softmax over K=64, one warp per row --------
__global__ void k_softmax(const float* __restrict__ s,
                          const int* __restrict__ mask) {
    int row = (blockIdx.x * blockDim.x + threadIdx.x) >> 5;
    if (row >= B_*N_) return;
    int lane = threadIdx.x & 31;
    const float* sr = s + (size_t)row * K_;
    float v0 = sr[lane], v1 = sr[lane + 32];
    float mx = fmaxf(v0, v1);
    #pragma unroll
    for (int o = 16; o; o >>= 1) mx = fmaxf(mx, __shfl_xor_sync(0xffffffffu, mx, o));
    float e0 = expf(v0 - mx), e1 = expf(v1 - mx);
    float sm = e0 + e1;
    #pragma unroll
    for (int o = 16; o; o >>= 1) sm += __shfl_xor_sync(0xffffffffu, sm, o);
    float m = (mask[row] != 0) ? 1.f : 0.f;
    float inv = m / sm;
    float p0 = e0 * inv, p1 = e1 * inv;
    g_P[(size_t)row * K_ + lane]      = p0;
    g_P[(size_t)row * K_ + lane + 32] = p1;
    float q = p0 * p0 + p1 * p1;
    #pragma unroll
    for (int o = 16; o; o >>= 1) q += __shfl_xor_sync(0xffffffffu, q, o);
    if (lane == 0) g_Q[row] = q;
}

// -------- out[b,k,f] = P^T x (scalar fp32), 64-row tiles --------
__global__ void __launch_bounds__(256) k_out_gemm(const float* __restrict__ x,
                                                  float* __restrict__ out) {
    int b = blockIdx.y;
    int row0 = blockIdx.x * 64;
    int rows = min(64, N_ - row0);
    __shared__ float Ps[32][64];
    __shared__ float Xs[32][128];
    int tid = threadIdx.x;
    int kq = tid & 15;
    int fq = tid >> 4;
    float acc[4][8] = {};
    const float* Pb = g_P + (size_t)b * N_ * K_ + (size_t)row0 * K_;
    const float* Xb = x   + (size_t)b * N_ * F_ + (size_t)row0 * F_;
    for (int t0 = 0; t0 < rows; t0 += 32) {
        #pragma unroll
        for (int i = 0; i < 8; i++) {
            int idx = tid + i * 256;
            int r = idx >> 6, c = idx & 63;
            Ps[r][c] = (t0 + r < rows) ? Pb[(size_t)(t0 + r) * K_ + c] : 0.f;
        }
        #pragma unroll
        for (int i = 0; i < 16; i++) {
            int idx = tid + i * 256;
            int r = idx >> 7, c = idx & 127;
            Xs[r][c] = (t0 + r < rows) ? Xb[(size_t)(t0 + r) * F_ + c] : 0.f;
        }
        __syncthreads();
        #pragma unroll 8
        for (int m = 0; m < 32; m++) {
            float4 pv  = *(const float4*)&Ps[m][kq * 4];
            float4 xv0 = *(const float4*)&Xs[m][fq * 8];
            float4 xv1 = *(const float4*)&Xs[m][fq * 8 + 4];
            float a[4]  = {pv.x, pv.y, pv.z, pv.w};
            float bb[8] = {xv0.x, xv0.y, xv0.z, xv0.w, xv1.x, xv1.y, xv1.z, xv1.w};
            #pragma unroll
            for (int i = 0; i < 4; i++)
                #pragma unroll
                for (int j = 0; j < 8; j++)
                    acc[i][j] = fmaf(a[i], bb[j], acc[i][j]);
        }
        __syncthreads();
    }
    float* ob = out + (size_t)b * K_ * F_;
    #pragma unroll
    for (int i = 0; i < 4; i++)
        #pragma unroll
        for (int j = 0; j < 8; j++)
            atomicAdd(&ob[(kq * 4 + i) * F_ + fq * 8 + j], acc[i][j]);
}

// -------- AS = adj @ P via wmma tf32, m-split x2, 512 CTAs --------
#define APAD 36
#define BPAD 68

__global__ void __launch_bounds__(256) k_adj_wmma(const float* __restrict__ adj) {
    __shared__ float As[64][APAD];
    __shared__ float Bs[TK_][BPAD];
    int tid = threadIdx.x;
    int warp = tid >> 5;
    int wm = warp >> 1;               // 0..3 (16-row tiles)
    int wn = warp & 1;                // 0..1 (32-col tiles)
    int b = blockIdx.y;
    int mc = blockIdx.z;              // m-chunk 0/1
    int row0 = blockIdx.x * 64;
    int rows = min(64, N_ - row0);    // 64 or 16

    int tstart = mc * TILES0;
    int tend   = mc ? NT_ : TILES0;

    const float* Ab = adj + (size_t)b * N_ * N_;
    const float* Pb = g_P + (size_t)b * N_ * K_;

    wmma::fragment<wmma::accumulator, 16, 16, 8, float> c[2];
    wmma::fill_fragment(c[0], 0.f);
    wmma::fill_fragment(c[1], 0.f);

    int ar = tid >> 2;                // A row 0..63
    int ac = (tid & 3) * 8;           // A col base (2 float4)
    float4 aR[2], bR[2];
    float dsum = 0.f;

    auto loadA = [&](int t) {
        int m0 = t * TK_;
        #pragma unroll
        for (int i = 0; i < 2; i++) {
            int cc = ac + i * 4;
            aR[i] = (ar < rows && m0 + cc < N_)
                  ? *(const float4*)&Ab[(size_t)(row0 + ar) * N_ + m0 + cc]
                  : make_float4(0.f, 0.f, 0.f, 0.f);
        }
    };
    auto loadB = [&](int t) {
        int m0 = t * TK_;
        #pragma unroll
        for (int i = 0; i < 2; i++) {
            int f4 = tid + i * 256;
            int r = f4 >> 4, c4 = (f4 & 15) * 4;
            bR[i] = (m0 + r < N_)
                  ? *(const float4*)&Pb[(size_t)(m0 + r) * K_ + c4]
                  : make_float4(0.f, 0.f, 0.f, 0.f);
        }
    };
    auto tf32x4 = [](float4 v) {
        return make_float4(wmma::__float_to_tf32(v.x), wmma::__float_to_tf32(v.y),
                           wmma::__float_to_tf32(v.z), wmma::__float_to_tf32(v.w));
    };

    loadA(tstart); loadB(tstart);
    for (int t = tstart; t < tend; t++) {
        #pragma unroll
        for (int i = 0; i < 2; i++) {
            dsum += aR[i].x + aR[i].y + aR[i].z + aR[i].w;
            *(float4*)&As[ar][ac + i * 4] = tf32x4(aR[i]);
        }
        #pragma unroll
        for (int i = 0; i < 2; i++) {
            int f4 = tid + i * 256;
            int r = f4 >> 4, c4 = (f4 & 15) * 4;
            *(float4*)&Bs[r][c4] = tf32x4(bR[i]);
        }
        __syncthreads();
        if (t + 1 < tend) { loadA(t + 1); loadB(t + 1); }   // overlap with MMA

        #pragma unroll
        for (int ks = 0; ks < 4; ks++) {
            wmma::fragment<wmma::matrix_a, 16, 16, 8, wmma::precision::tf32, wmma::row_major> af;
            wmma::fragment<wmma::matrix_b, 16, 16, 8, wmma::precision::tf32, wmma::row_major> bf[2];
            wmma::load_matrix_sync(af, &As[wm * 16][ks * 8], APAD);
            #pragma unroll
            for (int j = 0; j < 2; j++)
                wmma::load_matrix_sync(bf[j], &Bs[ks * 8][wn * 32 + j * 16], BPAD);
            #pragma unroll
            for (int j = 0; j < 2; j++)
                wmma::mma_sync(c[j], af, bf[j], c[j]);
        }
        __syncthreads();
    }

    // degree partial: 4 threads per row -> combine, store to chunk buffer
    dsum += __shfl_xor_sync(0xffffffffu, dsum, 1);
    dsum += __shfl_xor_sync(0xffffffffu, dsum, 2);
    float* Dp = mc ? g_D2 : g_D;
    if ((tid & 3) == 0 && ar < rows) Dp[b * N_ + row0 + ar] = dsum;

    // store fragments to chunk buffer
    float* ASb = (mc ? g_AS2 : g_AS) + ((size_t)b * N_ + row0) * K_;
    int r = wm * 16;
    if (r < rows) {
        #pragma unroll
        for (int j = 0; j < 2; j++)
            wmma::store_matrix_sync(&ASb[(size_t)r * K_ + wn * 32 + j * 16],
                                    c[j], K_, wmma::mem_row_major);
    }
}

// -------- out_adj = AS^T P, ss = P^T P, den = sum d*q (125-row chunks) --------
__global__ void __launch_bounds__(256) k_small(void) {
    int b = blockIdx.y;
    int n0 = blockIdx.x * 125;
    __shared__ float ASs[16][64];
    __shared__ float Ps[16][64];
    __shared__ float red[256];
    int tid = threadIdx.x;
    int kg = tid & 15;
    int lg = tid >> 4;
    float accA[4][4] = {};
    float accS[4][4] = {};
    const float* AS0 = g_AS  + (size_t)b * N_ * K_;
    const float* AS1 = g_AS2 + (size_t)b * N_ * K_;
    const float* Pb  = g_P   + (size_t)b * N_ * K_;
    for (int t0 = 0; t0 < 125; t0 += 16) {
        #pragma unroll
        for (int i = 0; i < 4; i++) {
            int idx = tid + i * 256;
            int r = idx >> 6, c = idx & 63;
            bool ok = (t0 + r) < 125;
            size_t g = (size_t)(n0 + t0 + r) * K_ + c;
            ASs[r][c] = ok ? (AS0[g] + AS1[g]) : 0.f;
            Ps[r][c]  = ok ? Pb[g] : 0.f;
        }
        __syncthreads();
        #pragma unroll 8
        for (int m = 0; m < 16; m++) {
            float4 ak = *(const float4*)&ASs[m][kg * 4];
            float4 pk = *(const float4*)&Ps[m][kg * 4];
            float4 pl = *(const float4*)&Ps[m][lg * 4];
            float a[4] = {ak.x, ak.y, ak.z, ak.w};
            float p[4] = {pk.x, pk.y, pk.z, pk.w};
            float q[4] = {pl.x, pl.y, pl.z, pl.w};
            #pragma unroll
            for (int i = 0; i < 4; i++)
                #pragma unroll
                for (int j = 0; j < 4; j++) {
                    accA[i][j] = fmaf(a[i], q[j], accA[i][j]);
                    accS[i][j] = fmaf(p[i], q[j], accS[i][j]);
                }
        }
        __syncthreads();
    }
    float* OA  = g_OUTADJ + b * K_ * K_;
    float* SSb = g_SS     + b * K_ * K_;
    #pragma unroll
    for (int i = 0; i < 4; i++)
        #pragma unroll
        for (int j = 0; j < 4; j++) {
            atomicAdd(&OA [(kg * 4 + i) * K_ + lg * 4 + j], accA[i][j]);
            atomicAdd(&SSb[(kg * 4 + i) * K_ + lg * 4 + j], accS[i][j]);
        }
    float dq = 0.f;
    for (int n = tid; n < 125; n += 256) {
        int gi = b * N_ + n0 + n;
        dq += (g_D[gi] + g_D2[gi]) * g_Q[gi];
    }
    red[tid] = dq; __syncthreads();
    for (int st = 128; st; st >>= 1) { if (tid < st) red[tid] += red[tid + st]; __syncthreads(); }
    if (tid == 0) atomicAdd(&g_DEN[b], red[0]);
}

// -------- per-batch finalize --------
__global__ void k_finalize(float* __restrict__ outadj_out) {
    int b = blockIdx.x;
    int tid = threadIdx.x;
    const float* OA  = g_OUTADJ + b * K_ * K_;
    const float* SSb = g_SS     + b * K_ * K_;
    __shared__ float red[256];
    __shared__ float s_frob, s_trace;
    __shared__ float dvec[K_];

    float fs = 0.f;
    for (int i = tid; i < K_*K_; i += 256) { float v = SSb[i]; fs += v * v; }
    red[tid] = fs; __syncthreads();
    for (int st = 128; st; st >>= 1) { if (tid < st) red[tid] += red[tid + st]; __syncthreads(); }
    if (tid == 0) s_frob = sqrtf(red[0]);
    __syncthreads();
    float frob = s_frob;

    float os = 0.f;
    for (int i = tid; i < K_*K_; i += 256) {
        int k = i >> 6, l = i & 63;
        float v = SSb[i] / frob - ((k == l) ? 0.125f : 0.f);
        os += v * v;
    }
    red[tid] = os; __syncthreads();
    for (int st = 128; st; st >>= 1) { if (tid < st) red[tid] += red[tid + st]; __syncthreads(); }
    float ortho = sqrtf(red[0]);
    __syncthreads();

    float tr = (tid < K_) ? OA[tid * K_ + tid] : 0.f;
    red[tid] = tr; __syncthreads();
    for (int st = 128; st; st >>= 1) { if (tid < st) red[tid] += red[tid + st]; __syncthreads(); }
    if (tid == 0) s_trace = red[0];
    __syncthreads();

    if (tid < K_) {
        float rs = 0.f;
        #pragma unroll
        for (int l = 0; l < K_; l++) if (l != tid) rs += OA[tid * K_ + l];
        dvec[tid] = sqrtf(rs) + 1e-15f;
    }
    __syncthreads();
    for (int i = tid; i < K_*K_; i += 256) {
        int k = i >> 6, l = i & 63;
        float v = (k == l) ? 0.f : OA[i] / (dvec[k] * dvec[l]);
        outadj_out[b * K_ * K_ + i] = v;
    }
    if (tid == 0) {
        g_LOSS[b]      = -(s_trace / g_DEN[b]);
        g_LOSS[B_ + b] = ortho;
    }
}

__global__ void k_losses(float* __restrict__ out2) {
    if (threadIdx.x == 0) {
        float a = 0.f, o = 0.f;
        #pragma unroll
        for (int b = 0; b < B_; b++) { a += g_LOSS[b]; o += g_LOSS[B_ + b]; }
        out2[0] = a * (1.f / B_);
        out2[1] = o * (1.f / B_);
    }
}

extern "C" void kernel_launch(void* const* d_in, const int* in_sizes, int n_in,
                              void* d_out, int out_size) {
    const float* x    = (const float*)d_in[0];   // [8,2000,128]
    const float* adj  = (const float*)d_in[1];   // [8,2000,2000]
    const float* s    = (const float*)d_in[2];   // [8,2000,64]
    const int*   mask = (const int*)d_in[3];     // [8,2000] bool->int32
    float* out = (float*)d_out;
    // layout: out [8,64,128] | out_adj [8,64,64] | mincut_loss | ortho_loss

    k_init<<<256, 256>>>(out);
    k_softmax<<<(B_*N_*32 + 255) / 256, 256>>>(s, mask);
    dim3 g2(32, B_);          k_out_gemm<<<g2, 256>>>(x, out);
    dim3 g3(32, B_, MSPLIT);  k_adj_wmma<<<g3, 256>>>(adj);
    dim3 g4(16, B_);          k_small<<<g4, 256>>>();
    k_finalize<<<B_, 256>>>(out + B_*K_*F_);
    k_losses<<<1, 32>>>(out + B_*K_*F_ + B_*K_*K_);
    (void)in_sizes; (void)n_in; (void)out_size;
}